// round 10
// baseline (speedup 1.0000x reference)
#include <cuda_runtime.h>
#include <cstdint>
#include <math.h>

#define DIM      128
#define NPARAMS  8384
#define NT       256            // 8 warps

// Two-region triangular L layout (floats), plain row-major columns:
//  region A: rows 0-63, 64 cols, stride 68
//  region B: rows 64-127, 128 cols, stride 132
#define RS_A     68
#define RS_B     132
#define OFF_A    0
#define OFF_B    (64 * RS_A)            // 4352
#define OFF_EPS  (OFF_B + 64 * RS_B)    // 12800
#define OFF_LD   (OFF_EPS + 128)
#define OFF_MEAN (OFF_LD + 128)
#define OFF_DIAG (OFF_MEAN + 128)
#define SMEM_FLOATS (OFF_DIAG + 128)    // 13312 floats = 53248 B

// Work items: bit6 = pair (tiles (mt,nt) and (mt+1,nt)), bits5:3 = mt,
// bits2:0 = nt. 0xFF = end. Per-warp MMA cost 56-64; all 36 tiles covered.
__constant__ uint8_t TILE_TAB[8][6] = {
    {0x76, 0x40, 0xFF, 0xFF, 0xFF, 0xFF},
    {0x6D, 0x49, 0xFF, 0xFF, 0xFF, 0xFF},
    {0x64, 0x52, 0xFF, 0xFF, 0xFF, 0xFF},
    {0x74, 0x62, 0xFF, 0xFF, 0xFF, 0xFF},
    {0x5B, 0x3D, 0xFF, 0xFF, 0xFF, 0xFF},
    {0x6B, 0x72, 0xFF, 0xFF, 0xFF, 0xFF},
    {0x3F, 0x3B, 0x50, 0xFF, 0xFF, 0xFF},
    {0x59, 0x69, 0x39, 0x60, 0x70, 0xFF},
};

__device__ __forceinline__ int rowbase(int r) {
    return (r < 64) ? (OFF_A + r * RS_A) : (OFF_B + (r - 64) * RS_B);
}

__device__ __forceinline__ void mma_tf32(float* d, uint32_t a0, uint32_t a1,
                                         uint32_t a2, uint32_t a3,
                                         uint32_t b0, uint32_t b1) {
    asm volatile(
        "mma.sync.aligned.m16n8k8.row.col.f32.tf32.tf32.f32 "
        "{%0,%1,%2,%3}, {%4,%5,%6,%7}, {%8,%9}, {%0,%1,%2,%3};"
        : "+f"(d[0]), "+f"(d[1]), "+f"(d[2]), "+f"(d[3])
        : "r"(a0), "r"(a1), "r"(a2), "r"(a3), "r"(b0), "r"(b1));
}

__device__ __forceinline__ uint32_t to_tf32(float v) {
    uint32_t t;
    asm("cvt.rna.tf32.f32 %0, %1;" : "=r"(t) : "f"(v));
    return t;
}

// Compile-time-trip GEMM inner loop for one (paired) work item.
template<int KS, bool PAIR, bool ALIAS>
__device__ __forceinline__ void gemm_item(const float* __restrict__ smf,
                                          float d0[2][4], float d1[2][4],
                                          int ar0, int ar1, int br0, int br1,
                                          int cr0, int cr1)
{
    #pragma unroll 4
    for (int ks = 0; ks < KS; ks++) {
        const int k0 = ks * 8;
        uint32_t a0 = *(const uint32_t*)&smf[ar0 + k0];
        uint32_t a2 = *(const uint32_t*)&smf[ar0 + k0 + 4];
        uint32_t a1 = *(const uint32_t*)&smf[ar1 + k0];
        uint32_t a3 = *(const uint32_t*)&smf[ar1 + k0 + 4];
        uint32_t b0x, b0y, b1x, b1y;
        if (ALIAS) {
            b0x = a0; b0y = a2; b1x = a1; b1y = a3;
        } else {
            b0x = *(const uint32_t*)&smf[br0 + k0];
            b0y = *(const uint32_t*)&smf[br0 + k0 + 4];
            b1x = *(const uint32_t*)&smf[br1 + k0];
            b1y = *(const uint32_t*)&smf[br1 + k0 + 4];
        }
        mma_tf32(d0[0], a0, a1, a2, a3, b0x, b0y);
        mma_tf32(d0[1], a0, a1, a2, a3, b1x, b1y);
        if (PAIR) {
            uint32_t c0 = *(const uint32_t*)&smf[cr0 + k0];
            uint32_t c2 = *(const uint32_t*)&smf[cr0 + k0 + 4];
            uint32_t c1 = *(const uint32_t*)&smf[cr1 + k0];
            uint32_t c3 = *(const uint32_t*)&smf[cr1 + k0 + 4];
            mma_tf32(d1[0], c0, c1, c2, c3, b0x, b0y);
            mma_tf32(d1[1], c0, c1, c2, c3, b1x, b1y);
        }
    }
}

// Transform one float4 chunk of row r (cols j0..j0+3) and store (tf32) to smem.
__device__ __forceinline__ void xform_store(float* smf, const int rbase,
                                            const int r, const int j0,
                                            const float rw, float4 v,
                                            bool has_data) {
    if (!has_data) {
        v = make_float4(0.f, 0.f, 0.f, 0.f);
    } else if (j0 + 3 < r) {
        v.x *= rw; v.y *= rw; v.z *= rw; v.w *= rw;
    } else {
        float vv[4] = {v.x, v.y, v.z, v.w};
        #pragma unroll
        for (int e = 0; e < 4; e++) {
            int j = j0 + e;
            float raw = vv[e];
            if (j < r)       vv[e] = raw * rw;
            else if (j == r) { smf[OFF_LD + r] = raw; vv[e] = expf(raw); }
            else             vv[e] = 0.0f;
        }
        v = make_float4(vv[0], vv[1], vv[2], vv[3]);
    }
    *(uint4*)&smf[rbase + j0] =
        make_uint4(to_tf32(v.x), to_tf32(v.y), to_tf32(v.z), to_tf32(v.w));
}

// Store one m16n16 tile: direct float2 stores; mirror via xor4 shuffles.
// 32-bit byte-offset addressing off a char* base.
__device__ __forceinline__ void store_tile(char* SgB, float* smf,
                                           const float d[2][4],
                                           int m0, int n0, int gr, int tg,
                                           bool diag) {
    const uint32_t rb = (uint32_t)(m0 + gr) * (DIM * 4);
    #pragma unroll
    for (int s = 0; s < 2; s++) {
        const uint32_t co = (uint32_t)(n0 + 8 * s + 2 * tg) * 4;
        *(float2*)(SgB + rb + co)               = make_float2(d[s][0], d[s][1]);
        *(float2*)(SgB + rb + 8 * DIM * 4 + co) = make_float2(d[s][2], d[s][3]);
    }
    if (!diag) {
        const int odd  = gr & 1;
        const uint32_t ct = (uint32_t)(m0 + (gr & ~1)) * 4;
        #pragma unroll
        for (int s = 0; s < 2; s++) {
            float q0 = __shfl_xor_sync(0xffffffffu, d[s][0], 4);
            float q1 = __shfl_xor_sync(0xffffffffu, d[s][1], 4);
            float q2 = __shfl_xor_sync(0xffffffffu, d[s][2], 4);
            float q3 = __shfl_xor_sync(0xffffffffu, d[s][3], 4);
            const uint32_t rt = (uint32_t)(n0 + 8 * s + 2 * tg + odd) * (DIM * 4);
            float2 w0 = odd ? make_float2(q1, d[s][1]) : make_float2(d[s][0], q0);
            float2 w1 = odd ? make_float2(q3, d[s][3]) : make_float2(d[s][2], q2);
            *(float2*)(SgB + rt + ct)      = w0;
            *(float2*)(SgB + rt + ct + 32) = w1;
        }
    } else if (2 * tg == (gr & ~1)) {
        int c = gr & 1;
        smf[OFF_DIAG + m0 + gr]     = d[0][c];
        smf[OFF_DIAG + m0 + gr + 8] = d[1][2 + c];
    }
}

__global__ __launch_bounds__(NT, 4)
void fld_mma_kernel(const float* __restrict__ params,
                    const float* __restrict__ eps,
                    float* __restrict__ sample,
                    float* __restrict__ kl,
                    float* __restrict__ sigma)
{
    extern __shared__ float smf[];

    const int b   = blockIdx.x;
    const int tid = threadIdx.x;
    const int wid = tid >> 5;
    const int lid = tid & 31;
    const int gr  = lid >> 2;
    const int tg  = lid & 3;
    const float* P = params + (size_t)b * NPARAMS;

    // ---- phase 0: mean, eps ----
    if (tid < DIM) {
        smf[OFF_MEAN + tid] = P[tid];
        smf[OFF_EPS + tid]  = eps[(size_t)b * DIM + tid];
    }

    // ---- phase 1: coalesced triangular unpack ----
    #pragma unroll
    for (int q = 0; q < 8; q++) {
        const int r  = 64 + wid + 8 * q;
        const int j0 = lid << 2;
        const int cb = (r & ~15) + 16;
        if (j0 < cb) {
            const float rw = rsqrtf((float)(r + 1));
            float4 v = make_float4(0.f, 0.f, 0.f, 0.f);
            const bool has = (j0 <= r);
            if (has) {
                float4 w4 = *(const float4*)(P + 16508 - 128 * r - j0);
                v = make_float4(w4.w, w4.z, w4.y, w4.x);
            }
            xform_store(smf, OFF_B + (r - 64) * RS_B, r, j0, rw, v, has);
        }
    }
    #pragma unroll
    for (int q = 0; q < 4; q++) {
        const int hw = lid >> 4;
        const int hl = lid & 15;
        const int rA = wid + 8 * q;
        const int r  = hw ? (63 - rA) : rA;
        const int j0 = hl << 2;
        const int cb = (r & ~15) + 16;
        if (j0 < cb) {
            const float rw = rsqrtf((float)(r + 1));
            float4 v = make_float4(0.f, 0.f, 0.f, 0.f);
            const bool has = (j0 <= r);
            if (has)
                v = *(const float4*)(P + 256 + 128 * r + j0);
            xform_store(smf, OFF_A + r * RS_A, r, j0, rw, v, has);
        }
    }
    __syncthreads();

    // ---- phase 2a: m32n16 paired / single tiles ----
    char* SgB = (char*)(sigma + (size_t)b * DIM * DIM);

    for (int t = 0; t < 6; t++) {
        const uint32_t code = TILE_TAB[wid][t];
        if (code == 0xFF) break;
        const bool pair = (code & 0x40) != 0;
        const int mt0 = (code >> 3) & 7;
        const int nt  = code & 7;
        const int n0  = nt * 16;
        const int m0a = mt0 * 16;
        const bool alias = (mt0 == nt);

        const int rs_a = (mt0 < 4) ? RS_A : RS_B;
        const int ar0 = rowbase(m0a + gr) + tg;
        const int ar1 = ar0 + 8 * rs_a;
        const int rs_c = (mt0 + 1 < 4) ? RS_A : RS_B;
        const int cr0 = rowbase(((mt0 + 1) & 7) * 16 + gr) + tg;
        const int cr1 = cr0 + 8 * rs_c;
        const int rs_b = (nt < 4) ? RS_A : RS_B;
        const int br0 = rowbase(n0 + gr) + tg;
        const int br1 = br0 + 8 * rs_b;

        float d0[2][4], d1[2][4];
        #pragma unroll
        for (int s = 0; s < 2; s++)
            #pragma unroll
            for (int c = 0; c < 4; c++) { d0[s][c] = 0.0f; d1[s][c] = 0.0f; }

        // Compile-time trip-count dispatch: key = pair<<4 | alias<<3 | nt.
        const int key = (pair ? 16 : 0) | (alias ? 8 : 0) | nt;
        switch (key) {
        case 16|8|0: gemm_item< 2,true ,true >(smf,d0,d1,ar0,ar1,br0,br1,cr0,cr1); break;
        case 16|8|1: gemm_item< 4,true ,true >(smf,d0,d1,ar0,ar1,br0,br1,cr0,cr1); break;
        case 16|8|2: gemm_item< 6,true ,true >(smf,d0,d1,ar0,ar1,br0,br1,cr0,cr1); break;
        case 16|8|3: gemm_item< 8,true ,true >(smf,d0,d1,ar0,ar1,br0,br1,cr0,cr1); break;
        case 16|8|4: gemm_item<10,true ,true >(smf,d0,d1,ar0,ar1,br0,br1,cr0,cr1); break;
        case 16|8|5: gemm_item<12,true ,true >(smf,d0,d1,ar0,ar1,br0,br1,cr0,cr1); break;
        case 16|8|6: gemm_item<14,true ,true >(smf,d0,d1,ar0,ar1,br0,br1,cr0,cr1); break;
        case 16|0|0: gemm_item< 2,true ,false>(smf,d0,d1,ar0,ar1,br0,br1,cr0,cr1); break;
        case 16|0|1: gemm_item< 4,true ,false>(smf,d0,d1,ar0,ar1,br0,br1,cr0,cr1); break;
        case 16|0|2: gemm_item< 6,true ,false>(smf,d0,d1,ar0,ar1,br0,br1,cr0,cr1); break;
        case 16|0|3: gemm_item< 8,true ,false>(smf,d0,d1,ar0,ar1,br0,br1,cr0,cr1); break;
        case 16|0|4: gemm_item<10,true ,false>(smf,d0,d1,ar0,ar1,br0,br1,cr0,cr1); break;
        case  8|7:   gemm_item<16,false,true >(smf,d0,d1,ar0,ar1,br0,br1,cr0,cr1); break;
        case  0|1:   gemm_item< 4,false,false>(smf,d0,d1,ar0,ar1,br0,br1,cr0,cr1); break;
        case  0|3:   gemm_item< 8,false,false>(smf,d0,d1,ar0,ar1,br0,br1,cr0,cr1); break;
        case  0|5:   gemm_item<12,false,false>(smf,d0,d1,ar0,ar1,br0,br1,cr0,cr1); break;
        default: break;
        }

        store_tile(SgB, smf, d0, m0a, n0, gr, tg, alias);
        if (pair)
            store_tile(SgB, smf, d1, m0a + 16, n0, gr, tg, false);
    }

    // ---- phase 2b: sample = mean + L*eps (2 threads per row) ----
    {
        const int u = tid >> 1, h = tid & 1;
        const int r = (u & 1) ? (127 - (u >> 1)) : (u >> 1);
        const int c4tot = (r >> 2) + 1;
        const int ch0   = (c4tot + 1) >> 1;
        const int cbeg  = h ? ch0 : 0;
        const int cend  = h ? c4tot : ch0;
        const int rbase = rowbase(r);
        float dot = 0.0f;
        for (int c = cbeg; c < cend; c++) {
            const int j0 = c << 2;
            float4 lv = *(const float4*)&smf[rbase + j0];
            float4 ev = *(const float4*)&smf[OFF_EPS + j0];
            dot = fmaf(lv.x, ev.x, dot);
            dot = fmaf(lv.y, ev.y, dot);
            dot = fmaf(lv.z, ev.z, dot);
            dot = fmaf(lv.w, ev.w, dot);
        }
        dot += __shfl_xor_sync(0xffffffffu, dot, 1);
        if (!h)
            sample[(size_t)b * DIM + r] = smf[OFF_MEAN + r] + dot;
    }
    __syncthreads();   // s_diag / s_ld complete

    // ---- phase 3: kl (warp 0) ----
    if (wid == 0) {
        float t = 0.0f;
        #pragma unroll
        for (int k = 0; k < 4; k++) {
            int rr = lid + 32 * k;
            float m = smf[OFF_MEAN + rr];
            t += smf[OFF_DIAG + rr] - 1.0f + m * m - 2.0f * smf[OFF_LD + rr];
        }
        #pragma unroll
        for (int o = 16; o > 0; o >>= 1)
            t += __shfl_down_sync(0xffffffffu, t, o);
        if (lid == 0) kl[b] = 0.5f * t;
    }
}

extern "C" void kernel_launch(void* const* d_in, const int* in_sizes, int n_in,
                              void* d_out, int out_size)
{
    const float* params = (const float*)d_in[0];
    const float* eps    = (const float*)d_in[1];
    const int B = in_sizes[0] / NPARAMS;

    float* out    = (float*)d_out;
    float* sample = out;                       // B * 128
    float* kl     = out + (size_t)B * DIM;     // B
    float* sigma  = kl + B;                    // B * 128 * 128

    const int smem = SMEM_FLOATS * sizeof(float);
    cudaFuncSetAttribute(fld_mma_kernel,
                         cudaFuncAttributeMaxDynamicSharedMemorySize, smem);
    fld_mma_kernel<<<B, NT, smem>>>(params, eps, sample, kl, sigma);
}

// round 11
// speedup vs baseline: 1.2828x; 1.2828x over previous
#include <cuda_runtime.h>
#include <cstdint>
#include <math.h>

#define DIM      128
#define NPARAMS  8384
#define NT       256            // 8 warps

// Two-region triangular L layout (floats), row stride ≡ 12 (mod 32) plus an
// 8-word skew on odd 8-row blocks -> conflict-free for A rows (m0+gr),
// aliased B rows (n0+gr), and permuted B rows (n0+4*(gr>>1)+(gr&1)(+2)).
//  region A: rows 0-63, 64 data cols, stride 76
//  region B: rows 64-127, 128 data cols, stride 140
#define RS_A     76
#define RS_B     140
#define OFF_B    (64 * RS_A)            // 4864
#define OFF_EPS  (OFF_B + 64 * RS_B)    // 13824 (tf32-rounded eps)
#define OFF_LD   (OFF_EPS + 128)        // 13952
#define OFF_MEAN (OFF_LD + 128)         // 14080
#define OFF_DIAG (OFF_MEAN + 128)       // 14208
#define SMEM_FLOATS (OFF_DIAG + 128)    // 14336 floats = 57344 B (7x8KB)

// Work items: bit6 = pair (tiles (mt,nt) and (mt+1,nt)), bits5:3 = mt,
// bits2:0 = nt. 0xFF = end. All 36 lower tiles covered exactly once.
__constant__ uint8_t TILE_TAB[8][6] = {
    {0x76, 0x40, 0xFF, 0xFF, 0xFF, 0xFF},
    {0x6D, 0x49, 0xFF, 0xFF, 0xFF, 0xFF},
    {0x64, 0x52, 0xFF, 0xFF, 0xFF, 0xFF},
    {0x74, 0x62, 0xFF, 0xFF, 0xFF, 0xFF},
    {0x5B, 0x3D, 0xFF, 0xFF, 0xFF, 0xFF},
    {0x6B, 0x72, 0xFF, 0xFF, 0xFF, 0xFF},
    {0x3F, 0x3B, 0x50, 0xFF, 0xFF, 0xFF},
    {0x59, 0x69, 0x39, 0x60, 0x70, 0xFF},
};

__device__ __forceinline__ int rowbase(int r) {
    int base = (r < 64) ? (r * RS_A) : (OFF_B + (r - 64) * RS_B);
    return base + (((r >> 3) & 1) << 3);     // 8-word parity skew
}

__device__ __forceinline__ void mma_tf32(float* d, uint32_t a0, uint32_t a1,
                                         uint32_t a2, uint32_t a3,
                                         uint32_t b0, uint32_t b1) {
    asm volatile(
        "mma.sync.aligned.m16n8k8.row.col.f32.tf32.tf32.f32 "
        "{%0,%1,%2,%3}, {%4,%5,%6,%7}, {%8,%9}, {%0,%1,%2,%3};"
        : "+f"(d[0]), "+f"(d[1]), "+f"(d[2]), "+f"(d[3])
        : "r"(a0), "r"(a1), "r"(a2), "r"(a3), "r"(b0), "r"(b1));
}

__device__ __forceinline__ uint32_t to_tf32(float v) {
    uint32_t t;
    asm("cvt.rna.tf32.f32 %0, %1;" : "=r"(t) : "f"(v));
    return t;
}

// Transform one float4 chunk of row r (cols j0..j0+3) and store (tf32) to smem.
__device__ __forceinline__ void xform_store(float* smf, const int rbase,
                                            const int r, const int j0,
                                            const float rw, float4 v,
                                            bool has_data) {
    if (!has_data) {
        v = make_float4(0.f, 0.f, 0.f, 0.f);
    } else if (j0 + 3 < r) {
        v.x *= rw; v.y *= rw; v.z *= rw; v.w *= rw;
    } else {
        float vv[4] = {v.x, v.y, v.z, v.w};
        #pragma unroll
        for (int e = 0; e < 4; e++) {
            int j = j0 + e;
            float raw = vv[e];
            if (j < r)       vv[e] = raw * rw;
            else if (j == r) { smf[OFF_LD + r] = raw; vv[e] = expf(raw); }
            else             vv[e] = 0.0f;
        }
        v = make_float4(vv[0], vv[1], vv[2], vv[3]);
    }
    *(uint4*)&smf[rbase + j0] =
        make_uint4(to_tf32(v.x), to_tf32(v.y), to_tf32(v.z), to_tf32(v.w));
}

// Old-layout off-diagonal store (direct float2 + xor4 mirror). Used for the
// second sub-tile of alias (diag-lead) pairs, where B is unpermuted.
__device__ __forceinline__ void store_old_offdiag(char* SgB, const float d[2][4],
                                                  int m0, int n0, int gr, int tg) {
    const uint32_t rb = (uint32_t)(m0 + gr) * (DIM * 4);
    #pragma unroll
    for (int s = 0; s < 2; s++) {
        const uint32_t co = (uint32_t)(n0 + 8 * s + 2 * tg) * 4;
        *(float2*)(SgB + rb + co)               = make_float2(d[s][0], d[s][1]);
        *(float2*)(SgB + rb + 8 * DIM * 4 + co) = make_float2(d[s][2], d[s][3]);
    }
    const int odd  = gr & 1;
    const uint32_t ct = (uint32_t)(m0 + (gr & ~1)) * 4;
    #pragma unroll
    for (int s = 0; s < 2; s++) {
        float q0 = __shfl_xor_sync(0xffffffffu, d[s][0], 4);
        float q1 = __shfl_xor_sync(0xffffffffu, d[s][1], 4);
        float q2 = __shfl_xor_sync(0xffffffffu, d[s][2], 4);
        float q3 = __shfl_xor_sync(0xffffffffu, d[s][3], 4);
        const uint32_t rt = (uint32_t)(n0 + 8 * s + 2 * tg + odd) * (DIM * 4);
        float2 w0 = odd ? make_float2(q1, d[s][1]) : make_float2(d[s][0], q0);
        float2 w1 = odd ? make_float2(q3, d[s][3]) : make_float2(d[s][2], q2);
        *(float2*)(SgB + rt + ct)      = w0;
        *(float2*)(SgB + rt + ct + 32) = w1;
    }
}

// Permuted-layout store: thread owns logical cols n0+4tg..+3 for rows
// m0+gr and m0+8+gr -> 2x STG.128 direct; mirror = 8x scalar STG.32.
__device__ __forceinline__ void store_perm(char* SgB, const float d[2][4],
                                           int m0, int n0, int gr, int tg) {
    const uint32_t co = (uint32_t)(n0 + 4 * tg) * 4;
    *(float4*)(SgB + (uint32_t)(m0 + gr) * (DIM * 4) + co) =
        make_float4(d[0][0], d[0][1], d[1][0], d[1][1]);
    *(float4*)(SgB + (uint32_t)(m0 + 8 + gr) * (DIM * 4) + co) =
        make_float4(d[0][2], d[0][3], d[1][2], d[1][3]);
    const uint32_t cm = (uint32_t)(m0 + gr) * 4;
    #pragma unroll
    for (int s = 0; s < 2; s++)
        #pragma unroll
        for (int e = 0; e < 2; e++) {
            const uint32_t rw = (uint32_t)(n0 + 4 * tg + 2 * s + e) * (DIM * 4);
            *(float*)(SgB + rw + cm)      = d[s][e];
            *(float*)(SgB + rw + cm + 32) = d[s][2 + e];
        }
}

__global__ __launch_bounds__(NT, 4)
void fld_mma_kernel(const float* __restrict__ params,
                    const float* __restrict__ eps,
                    float* __restrict__ sample,
                    float* __restrict__ kl,
                    float* __restrict__ sigma)
{
    extern __shared__ float smf[];

    const int b   = blockIdx.x;
    const int tid = threadIdx.x;
    const int wid = tid >> 5;
    const int lid = tid & 31;
    const int gr  = lid >> 2;
    const int tg  = lid & 3;
    const float* P = params + (size_t)b * NPARAMS;

    // ---- phase 0: mean, eps (tf32-rounded) ----
    if (tid < DIM) {
        smf[OFF_MEAN + tid] = P[tid];
        *(uint32_t*)&smf[OFF_EPS + tid] = to_tf32(eps[(size_t)b * DIM + tid]);
    }

    // ---- phase 1: coalesced triangular unpack ----
    //   r < 64 : P[256 + 128r + j], ascending
    //   r >= 64: P[16511 - 128r - j], descending (float4 + register reverse)
    #pragma unroll
    for (int q = 0; q < 8; q++) {
        const int r  = 64 + wid + 8 * q;
        const int j0 = lid << 2;
        const int cb = (r & ~15) + 16;
        if (j0 < cb) {
            const float rw = rsqrtf((float)(r + 1));
            float4 v = make_float4(0.f, 0.f, 0.f, 0.f);
            const bool has = (j0 <= r);
            if (has) {
                float4 w4 = *(const float4*)(P + 16508 - 128 * r - j0);
                v = make_float4(w4.w, w4.z, w4.y, w4.x);
            }
            xform_store(smf, rowbase(r), r, j0, rw, v, has);
        }
    }
    #pragma unroll
    for (int q = 0; q < 4; q++) {
        const int hw = lid >> 4;
        const int hl = lid & 15;
        const int rA = wid + 8 * q;
        const int r  = hw ? (63 - rA) : rA;
        const int j0 = hl << 2;
        const int cb = (r & ~15) + 16;
        if (j0 < cb) {
            const float rw = rsqrtf((float)(r + 1));
            float4 v = make_float4(0.f, 0.f, 0.f, 0.f);
            const bool has = (j0 <= r);
            if (has)
                v = *(const float4*)(P + 256 + 128 * r + j0);
            xform_store(smf, rowbase(r), r, j0, rw, v, has);
        }
    }
    __syncthreads();

    // ---- phase 2: m32n16 paired / single tiles; sample fused into diag ----
    char* SgB = (char*)(sigma + (size_t)b * DIM * DIM);

    for (int t = 0; t < 6; t++) {
        const uint32_t code = TILE_TAB[wid][t];
        if (code == 0xFF) break;
        const bool pair = (code & 0x40) != 0;
        const int mt0 = (code >> 3) & 7;
        const int nt  = code & 7;
        const int n0  = nt * 16;
        const int m0a = mt0 * 16;
        const bool alias = (mt0 == nt);
        const int ksteps = 2 * (nt + 1);

        const int ar0 = rowbase(m0a + gr) + tg;
        const int ar1 = rowbase(m0a + 8 + gr) + tg;
        const int cr0 = rowbase(((m0a + 16) & 127) + gr) + tg;
        const int cr1 = rowbase(((m0a + 24) & 127) + gr) + tg;

        float d0[2][4], d1[2][4];
        #pragma unroll
        for (int s = 0; s < 2; s++)
            #pragma unroll
            for (int c = 0; c < 4; c++) { d0[s][c] = 0.0f; d1[s][c] = 0.0f; }

        if (alias) {
            // diag-lead item: B aliases A (unpermuted); fused eps column.
            float de[4] = {0.f, 0.f, 0.f, 0.f};
            #pragma unroll 2
            for (int ks = 0; ks < ksteps; ks++) {
                const int k0 = ks * 8;
                uint32_t a0 = *(const uint32_t*)&smf[ar0 + k0];
                uint32_t a2 = *(const uint32_t*)&smf[ar0 + k0 + 4];
                uint32_t a1 = *(const uint32_t*)&smf[ar1 + k0];
                uint32_t a3 = *(const uint32_t*)&smf[ar1 + k0 + 4];
                mma_tf32(d0[0], a0, a1, a2, a3, a0, a2);
                mma_tf32(d0[1], a0, a1, a2, a3, a1, a3);
                uint32_t ex = 0, ey = 0;
                if (gr == 0) {
                    ex = *(const uint32_t*)&smf[OFF_EPS + k0 + tg];
                    ey = *(const uint32_t*)&smf[OFF_EPS + k0 + tg + 4];
                }
                mma_tf32(de, a0, a1, a2, a3, ex, ey);
                if (pair) {
                    uint32_t c0 = *(const uint32_t*)&smf[cr0 + k0];
                    uint32_t c2 = *(const uint32_t*)&smf[cr0 + k0 + 4];
                    uint32_t c1 = *(const uint32_t*)&smf[cr1 + k0];
                    uint32_t c3 = *(const uint32_t*)&smf[cr1 + k0 + 4];
                    mma_tf32(d1[0], c0, c1, c2, c3, a0, a2);
                    mma_tf32(d1[1], c0, c1, c2, c3, a1, a3);
                }
            }
            // sample (output column 0 lives in tg==0 lanes)
            if (tg == 0) {
                sample[(size_t)b * DIM + m0a + gr] =
                    smf[OFF_MEAN + m0a + gr] + de[0];
                sample[(size_t)b * DIM + m0a + 8 + gr] =
                    smf[OFF_MEAN + m0a + 8 + gr] + de[2];
            }
            // diag tile direct store (old layout) + Sigma-diagonal extraction
            {
                const uint32_t rb = (uint32_t)(m0a + gr) * (DIM * 4);
                #pragma unroll
                for (int s = 0; s < 2; s++) {
                    const uint32_t co = (uint32_t)(n0 + 8 * s + 2 * tg) * 4;
                    *(float2*)(SgB + rb + co) =
                        make_float2(d0[s][0], d0[s][1]);
                    *(float2*)(SgB + rb + 8 * DIM * 4 + co) =
                        make_float2(d0[s][2], d0[s][3]);
                }
                if (2 * tg == (gr & ~1)) {
                    int c = gr & 1;
                    smf[OFF_DIAG + m0a + gr]     = d0[0][c];
                    smf[OFF_DIAG + m0a + gr + 8] = d0[1][2 + c];
                }
            }
            if (pair)
                store_old_offdiag(SgB, d1, m0a + 16, n0, gr, tg);
        } else {
            // permuted B rows -> thread owns 4 consecutive output columns
            const int pg  = ((gr >> 1) << 2) | (gr & 1);
            const int br0 = rowbase(n0 + pg) + tg;
            const int br1 = rowbase(n0 + pg + 2) + tg;
            #pragma unroll 2
            for (int ks = 0; ks < ksteps; ks++) {
                const int k0 = ks * 8;
                uint32_t a0 = *(const uint32_t*)&smf[ar0 + k0];
                uint32_t a2 = *(const uint32_t*)&smf[ar0 + k0 + 4];
                uint32_t a1 = *(const uint32_t*)&smf[ar1 + k0];
                uint32_t a3 = *(const uint32_t*)&smf[ar1 + k0 + 4];
                uint32_t b0x = *(const uint32_t*)&smf[br0 + k0];
                uint32_t b0y = *(const uint32_t*)&smf[br0 + k0 + 4];
                uint32_t b1x = *(const uint32_t*)&smf[br1 + k0];
                uint32_t b1y = *(const uint32_t*)&smf[br1 + k0 + 4];
                mma_tf32(d0[0], a0, a1, a2, a3, b0x, b0y);
                mma_tf32(d0[1], a0, a1, a2, a3, b1x, b1y);
                if (pair) {
                    uint32_t c0 = *(const uint32_t*)&smf[cr0 + k0];
                    uint32_t c2 = *(const uint32_t*)&smf[cr0 + k0 + 4];
                    uint32_t c1 = *(const uint32_t*)&smf[cr1 + k0];
                    uint32_t c3 = *(const uint32_t*)&smf[cr1 + k0 + 4];
                    mma_tf32(d1[0], c0, c1, c2, c3, b0x, b0y);
                    mma_tf32(d1[1], c0, c1, c2, c3, b1x, b1y);
                }
            }
            store_perm(SgB, d0, m0a, n0, gr, tg);
            if (pair)
                store_perm(SgB, d1, m0a + 16, n0, gr, tg);
        }
    }
    __syncthreads();   // OFF_DIAG / OFF_LD complete

    // ---- phase 3: kl (warp 0) ----
    if (wid == 0) {
        float t = 0.0f;
        #pragma unroll
        for (int k = 0; k < 4; k++) {
            int rr = lid + 32 * k;
            float m = smf[OFF_MEAN + rr];
            t += smf[OFF_DIAG + rr] - 1.0f + m * m - 2.0f * smf[OFF_LD + rr];
        }
        #pragma unroll
        for (int o = 16; o > 0; o >>= 1)
            t += __shfl_down_sync(0xffffffffu, t, o);
        if (lid == 0) kl[b] = 0.5f * t;
    }
}

extern "C" void kernel_launch(void* const* d_in, const int* in_sizes, int n_in,
                              void* d_out, int out_size)
{
    const float* params = (const float*)d_in[0];
    const float* eps    = (const float*)d_in[1];
    const int B = in_sizes[0] / NPARAMS;

    float* out    = (float*)d_out;
    float* sample = out;                       // B * 128
    float* kl     = out + (size_t)B * DIM;     // B
    float* sigma  = kl + B;                    // B * 128 * 128

    const int smem = SMEM_FLOATS * sizeof(float);
    cudaFuncSetAttribute(fld_mma_kernel,
                         cudaFuncAttributeMaxDynamicSharedMemorySize, smem);
    fld_mma_kernel<<<B, NT, smem>>>(params, eps, sample, kl, sigma);
}

// round 14
// speedup vs baseline: 1.4844x; 1.1571x over previous
#include <cuda_runtime.h>
#include <cstdint>
#include <math.h>

#define DIM      128
#define NPARAMS  8384
#define NT       256            // 8 warps

// Triangular k-interleaved L layout. 16-row group g (rows 16g..16g+15)
// stores 16(g+1) data cols, stride GS[g] (all ≡ 24 mod 32, and
// GS[g] >= 16(g+1)+16 so the +16 skew never overlaps the next row),
// group base GB[g] (≡ 0 mod 32), plus +16 float skew when (r&4).
// Within each 8-col k-group, logical order [k0,k4,k1,k5,k2,k6,k3,k7]
// -> fragment pair (k+tg, k+tg+4) is one LDS.64 at phys offset 2*tg.
__constant__ int GB[8] = {0, 896, 1792, 3200, 4608, 6528, 8448, 10880};
__constant__ int GS[8] = {56, 56, 88, 88, 120, 120, 152, 152};

#define OFF_EPS  13312          // eps, tf32, k-interleaved, 128
#define OFF_LD   13440          // log-diag, 128
#define OFF_MEAN 13568
#define OFF_DIAG 13696
#define SMEM_FLOATS 13824       // 55296 B -> 4 CTAs/SM

// Work items: bit6 = pair (tiles (mt,nt),(mt+1,nt)), bits5:3 = mt, bits2:0 = nt.
__constant__ uint8_t TILE_TAB[8][6] = {
    {0x76, 0x40, 0xFF, 0xFF, 0xFF, 0xFF},
    {0x6D, 0x49, 0xFF, 0xFF, 0xFF, 0xFF},
    {0x64, 0x52, 0xFF, 0xFF, 0xFF, 0xFF},
    {0x74, 0x62, 0xFF, 0xFF, 0xFF, 0xFF},
    {0x5B, 0x3D, 0xFF, 0xFF, 0xFF, 0xFF},
    {0x6B, 0x72, 0xFF, 0xFF, 0xFF, 0xFF},
    {0x3F, 0x3B, 0x50, 0xFF, 0xFF, 0xFF},
    {0x59, 0x69, 0x39, 0x60, 0x70, 0xFF},
};

__device__ __forceinline__ int rowbase(int r) {
    const int g = r >> 4;
    return GB[g] + (r & 15) * GS[g] + ((r & 4) << 2);
}

__device__ __forceinline__ void mma_tf32(float* d, uint32_t a0, uint32_t a1,
                                         uint32_t a2, uint32_t a3,
                                         uint32_t b0, uint32_t b1) {
    asm volatile(
        "mma.sync.aligned.m16n8k8.row.col.f32.tf32.tf32.f32 "
        "{%0,%1,%2,%3}, {%4,%5,%6,%7}, {%8,%9}, {%0,%1,%2,%3};"
        : "+f"(d[0]), "+f"(d[1]), "+f"(d[2]), "+f"(d[3])
        : "r"(a0), "r"(a1), "r"(a2), "r"(a3), "r"(b0), "r"(b1));
}

__device__ __forceinline__ uint32_t to_tf32(float v) {
    uint32_t t;
    asm("cvt.rna.tf32.f32 %0, %1;" : "=r"(t) : "f"(v));
    return t;
}

// Transform 4 logical cols j0..j0+3 of row r (scale/exp/zero); save log-diag.
__device__ __forceinline__ float4 xform4(float* smf, int r, int j0,
                                         float rw, float4 v) {
    if (j0 + 3 < r) {
        v.x *= rw; v.y *= rw; v.z *= rw; v.w *= rw;
    } else {
        float vv[4] = {v.x, v.y, v.z, v.w};
        #pragma unroll
        for (int e = 0; e < 4; e++) {
            int j = j0 + e;
            float raw = vv[e];
            if (j < r)       vv[e] = raw * rw;
            else if (j == r) { smf[OFF_LD + r] = raw; vv[e] = expf(raw); }
            else             vv[e] = 0.0f;
        }
        v = make_float4(vv[0], vv[1], vv[2], vv[3]);
    }
    return v;
}

// Process one 8-col chunk of row r: transform + interleave-pack + 2x STS.128.
__device__ __forceinline__ void chunk_store(float* smf, const float* P,
                                            int r, int j0, float rw) {
    float4 lo = make_float4(0.f, 0.f, 0.f, 0.f);
    float4 hi = make_float4(0.f, 0.f, 0.f, 0.f);
    if (j0 <= r) {
        if (r < 64) {
            lo = *(const float4*)(P + 256 + 128 * r + j0);
            hi = *(const float4*)(P + 256 + 128 * r + j0 + 4);
        } else {
            float4 a = *(const float4*)(P + 16508 - 128 * r - j0);
            float4 b = *(const float4*)(P + 16504 - 128 * r - j0);
            lo = make_float4(a.w, a.z, a.y, a.x);
            hi = make_float4(b.w, b.z, b.y, b.x);
        }
        lo = xform4(smf, r, j0, rw, lo);
        hi = xform4(smf, r, j0 + 4, rw, hi);
    }
    const int rb = rowbase(r) + j0;
    *(uint4*)&smf[rb] = make_uint4(to_tf32(lo.x), to_tf32(hi.x),
                                   to_tf32(lo.y), to_tf32(hi.y));
    *(uint4*)&smf[rb + 4] = make_uint4(to_tf32(lo.z), to_tf32(hi.z),
                                       to_tf32(lo.w), to_tf32(hi.w));
}

// Old-layout off-diagonal store (direct float2 + xor4 mirror) for the
// second sub-tile of diag-lead pairs.
__device__ __forceinline__ void store_old_offdiag(char* SgB, const float d[2][4],
                                                  int m0, int n0, int gr, int tg) {
    const uint32_t rb = (uint32_t)(m0 + gr) * (DIM * 4);
    #pragma unroll
    for (int s = 0; s < 2; s++) {
        const uint32_t co = (uint32_t)(n0 + 8 * s + 2 * tg) * 4;
        *(float2*)(SgB + rb + co)               = make_float2(d[s][0], d[s][1]);
        *(float2*)(SgB + rb + 8 * DIM * 4 + co) = make_float2(d[s][2], d[s][3]);
    }
    const int odd  = gr & 1;
    const uint32_t ct = (uint32_t)(m0 + (gr & ~1)) * 4;
    #pragma unroll
    for (int s = 0; s < 2; s++) {
        float q0 = __shfl_xor_sync(0xffffffffu, d[s][0], 4);
        float q1 = __shfl_xor_sync(0xffffffffu, d[s][1], 4);
        float q2 = __shfl_xor_sync(0xffffffffu, d[s][2], 4);
        float q3 = __shfl_xor_sync(0xffffffffu, d[s][3], 4);
        const uint32_t rt = (uint32_t)(n0 + 8 * s + 2 * tg + odd) * (DIM * 4);
        float2 w0 = odd ? make_float2(q1, d[s][1]) : make_float2(d[s][0], q0);
        float2 w1 = odd ? make_float2(q3, d[s][3]) : make_float2(d[s][2], q2);
        *(float2*)(SgB + rt + ct)      = w0;
        *(float2*)(SgB + rt + ct + 32) = w1;
    }
}

// Permuted-layout store: 2x STG.128 direct + 8x scalar mirror.
__device__ __forceinline__ void store_perm(char* SgB, const float d[2][4],
                                           int m0, int n0, int gr, int tg) {
    const uint32_t co = (uint32_t)(n0 + 4 * tg) * 4;
    *(float4*)(SgB + (uint32_t)(m0 + gr) * (DIM * 4) + co) =
        make_float4(d[0][0], d[0][1], d[1][0], d[1][1]);
    *(float4*)(SgB + (uint32_t)(m0 + 8 + gr) * (DIM * 4) + co) =
        make_float4(d[0][2], d[0][3], d[1][2], d[1][3]);
    const uint32_t cm = (uint32_t)(m0 + gr) * 4;
    #pragma unroll
    for (int s = 0; s < 2; s++)
        #pragma unroll
        for (int e = 0; e < 2; e++) {
            const uint32_t rw = (uint32_t)(n0 + 4 * tg + 2 * s + e) * (DIM * 4);
            *(float*)(SgB + rw + cm)      = d[s][e];
            *(float*)(SgB + rw + cm + 32) = d[s][2 + e];
        }
}

__global__ __launch_bounds__(NT, 4)
void fld_mma_kernel(const float* __restrict__ params,
                    const float* __restrict__ eps,
                    float* __restrict__ sample,
                    float* __restrict__ kl,
                    float* __restrict__ sigma)
{
    extern __shared__ float smf[];

    const int b   = blockIdx.x;
    const int tid = threadIdx.x;
    const int wid = tid >> 5;
    const int lid = tid & 31;
    const int gr  = lid >> 2;
    const int tg  = lid & 3;
    const float* P = params + (size_t)b * NPARAMS;

    // ---- phase 0: mean, eps (tf32, k-interleaved) ----
    if (tid < DIM) {
        smf[OFF_MEAN + tid] = P[tid];
        const int lo3 = tid & 7;
        const int phys = (tid & ~7) | ((lo3 < 4) ? (lo3 << 1) : (((lo3 - 4) << 1) | 1));
        *(uint32_t*)&smf[OFF_EPS + phys] = to_tf32(eps[(size_t)b * DIM + tid]);
    }

    // ---- phase 1: coalesced triangular unpack (8-col chunks) ----
    // rows >= 64: 2 rows per warp (half-warps), 4 iterations
    #pragma unroll
    for (int q = 0; q < 4; q++) {
        const int r  = 64 + wid + 8 * q + 32 * (lid >> 4);
        const int c  = lid & 15;
        const int j0 = c << 3;
        if (j0 < (r & ~15) + 16) {
            const float rw = rsqrtf((float)(r + 1));
            chunk_store(smf, P, r, j0, rw);
        }
    }
    // rows < 64: 4 rows per warp, 2 iterations (second reversed for balance)
    #pragma unroll
    for (int q = 0; q < 2; q++) {
        const int base = wid * 4 + (lid >> 3);
        const int r  = q ? (63 - base) : base;
        const int j0 = (lid & 7) << 3;
        if (j0 < (r & ~15) + 16) {
            const float rw = rsqrtf((float)(r + 1));
            chunk_store(smf, P, r, j0, rw);
        }
    }
    __syncthreads();

    // ---- phase 2: m32n16 paired / single tiles; sample fused into diag ----
    char* SgB = (char*)(sigma + (size_t)b * DIM * DIM);

    for (int t = 0; t < 6; t++) {
        const uint32_t code = TILE_TAB[wid][t];
        if (code == 0xFF) break;
        const bool pair = (code & 0x40) != 0;
        const int mt0 = (code >> 3) & 7;
        const int nt  = code & 7;
        const int n0  = nt * 16;
        const int m0a = mt0 * 16;
        const bool alias = (mt0 == nt);
        const int ksteps = 2 * (nt + 1);

        const int ar0 = rowbase(m0a + gr) + 2 * tg;
        const int ar1 = rowbase(m0a + 8 + gr) + 2 * tg;
        const int cr0 = rowbase(((m0a + 16) & 127) + gr) + 2 * tg;
        const int cr1 = rowbase(((m0a + 24) & 127) + gr) + 2 * tg;

        float d0[2][4], d1[2][4];
        #pragma unroll
        for (int s = 0; s < 2; s++)
            #pragma unroll
            for (int c = 0; c < 4; c++) { d0[s][c] = 0.0f; d1[s][c] = 0.0f; }

        if (alias) {
            // diag-lead: B aliases A; fused eps column for sample.
            float de[4] = {0.f, 0.f, 0.f, 0.f};
            #pragma unroll 2
            for (int ks = 0; ks < ksteps; ks++) {
                const int k0 = ks * 8;
                uint2 A0 = *(const uint2*)&smf[ar0 + k0];   // (a0, a2)
                uint2 A1 = *(const uint2*)&smf[ar1 + k0];   // (a1, a3)
                mma_tf32(d0[0], A0.x, A1.x, A0.y, A1.y, A0.x, A0.y);
                mma_tf32(d0[1], A0.x, A1.x, A0.y, A1.y, A1.x, A1.y);
                uint2 E = make_uint2(0u, 0u);
                if (gr == 0)
                    E = *(const uint2*)&smf[OFF_EPS + k0 + 2 * tg];
                mma_tf32(de, A0.x, A1.x, A0.y, A1.y, E.x, E.y);
                if (pair) {
                    uint2 C0 = *(const uint2*)&smf[cr0 + k0];
                    uint2 C1 = *(const uint2*)&smf[cr1 + k0];
                    mma_tf32(d1[0], C0.x, C1.x, C0.y, C1.y, A0.x, A0.y);
                    mma_tf32(d1[1], C0.x, C1.x, C0.y, C1.y, A1.x, A1.y);
                }
            }
            if (tg == 0) {
                sample[(size_t)b * DIM + m0a + gr] =
                    smf[OFF_MEAN + m0a + gr] + de[0];
                sample[(size_t)b * DIM + m0a + 8 + gr] =
                    smf[OFF_MEAN + m0a + 8 + gr] + de[2];
            }
            {
                const uint32_t rb = (uint32_t)(m0a + gr) * (DIM * 4);
                #pragma unroll
                for (int s = 0; s < 2; s++) {
                    const uint32_t co = (uint32_t)(n0 + 8 * s + 2 * tg) * 4;
                    *(float2*)(SgB + rb + co) =
                        make_float2(d0[s][0], d0[s][1]);
                    *(float2*)(SgB + rb + 8 * DIM * 4 + co) =
                        make_float2(d0[s][2], d0[s][3]);
                }
                if (2 * tg == (gr & ~1)) {
                    int c = gr & 1;
                    smf[OFF_DIAG + m0a + gr]     = d0[0][c];
                    smf[OFF_DIAG + m0a + gr + 8] = d0[1][2 + c];
                }
            }
            if (pair)
                store_old_offdiag(SgB, d1, m0a + 16, n0, gr, tg);
        } else {
            // permuted B rows -> thread owns 4 consecutive output columns
            const int pg  = ((gr >> 1) << 2) | (gr & 1);
            const int br0 = rowbase(n0 + pg) + 2 * tg;
            const int br1 = rowbase(n0 + pg + 2) + 2 * tg;
            #pragma unroll 2
            for (int ks = 0; ks < ksteps; ks++) {
                const int k0 = ks * 8;
                uint2 A0 = *(const uint2*)&smf[ar0 + k0];
                uint2 A1 = *(const uint2*)&smf[ar1 + k0];
                uint2 B0 = *(const uint2*)&smf[br0 + k0];
                uint2 B1 = *(const uint2*)&smf[br1 + k0];
                mma_tf32(d0[0], A0.x, A1.x, A0.y, A1.y, B0.x, B0.y);
                mma_tf32(d0[1], A0.x, A1.x, A0.y, A1.y, B1.x, B1.y);
                if (pair) {
                    uint2 C0 = *(const uint2*)&smf[cr0 + k0];
                    uint2 C1 = *(const uint2*)&smf[cr1 + k0];
                    mma_tf32(d1[0], C0.x, C1.x, C0.y, C1.y, B0.x, B0.y);
                    mma_tf32(d1[1], C0.x, C1.x, C0.y, C1.y, B1.x, B1.y);
                }
            }
            store_perm(SgB, d0, m0a, n0, gr, tg);
            if (pair)
                store_perm(SgB, d1, m0a + 16, n0, gr, tg);
        }
    }
    __syncthreads();   // OFF_DIAG / OFF_LD complete

    // ---- phase 3: kl (warp 0) ----
    if (wid == 0) {
        float t = 0.0f;
        #pragma unroll
        for (int k = 0; k < 4; k++) {
            int rr = lid + 32 * k;
            float m = smf[OFF_MEAN + rr];
            t += smf[OFF_DIAG + rr] - 1.0f + m * m - 2.0f * smf[OFF_LD + rr];
        }
        #pragma unroll
        for (int o = 16; o > 0; o >>= 1)
            t += __shfl_down_sync(0xffffffffu, t, o);
        if (lid == 0) kl[b] = 0.5f * t;
    }
}

extern "C" void kernel_launch(void* const* d_in, const int* in_sizes, int n_in,
                              void* d_out, int out_size)
{
    const float* params = (const float*)d_in[0];
    const float* eps    = (const float*)d_in[1];
    const int B = in_sizes[0] / NPARAMS;

    float* out    = (float*)d_out;
    float* sample = out;                       // B * 128
    float* kl     = out + (size_t)B * DIM;     // B
    float* sigma  = kl + B;                    // B * 128 * 128

    const int smem = SMEM_FLOATS * sizeof(float);
    cudaFuncSetAttribute(fld_mma_kernel,
                         cudaFuncAttributeMaxDynamicSharedMemorySize, smem);
    fld_mma_kernel<<<B, NT, smem>>>(params, eps, sample, kl, sigma);
}